// round 12
// baseline (speedup 1.0000x reference)
#include <cuda_runtime.h>
#include <cstdint>

#define NN 50000      // nodes
#define NE 800000     // edges
#define NP 50048      // nodes padded to multiple of 128
#define NB 98         // scan blocks: ceil(NP/512)
#define ED 64         // edge feature dim
#define HID 152
#define PK2_1 112     // layer-1 K pairs (224 floats, padded)
#define PK2_2 192     // layer-2/3 K pairs (384 floats)

// ---------------- scratch (device globals; no allocation allowed) ----------
__device__ int   g_cnt[NP];
__device__ int   g_fill[NP];
__device__ int   g_base[NP + 1];
__device__ int   g_bsum[128];
__device__ int   g_src[NE];
__device__ int   g_eid[NE];
__device__ float g_eagg[(size_t)NP * ED];
__device__ float g_h1[(size_t)NP * HID];
__device__ float g_h2[(size_t)NP * HID];
// pre-split bf16x2 hi/lo GEMM inputs
__device__ uint32_t g_xh1[(size_t)NP * PK2_1];
__device__ uint32_t g_xl1[(size_t)NP * PK2_1];
__device__ uint32_t g_xh2[(size_t)NP * PK2_2];
__device__ uint32_t g_xl2[(size_t)NP * PK2_2];
// fused weights: float intermediates + split versions
__device__ float    g_wc1[192 * 224];
__device__ float    g_wc2[192 * 384];
__device__ float    g_wc3[64 * 384];
__device__ uint32_t g_wh1[192 * PK2_1], g_wl1[192 * PK2_1];
__device__ uint32_t g_wh2[192 * PK2_2], g_wl2[192 * PK2_2];
__device__ uint32_t g_wh3[64 * PK2_2],  g_wl3[64 * PK2_2];

// ---------------- bf16 hi/lo split helpers ----------------------------------
__device__ __forceinline__ uint32_t pack_bf16x2(float f_even, float f_odd) {
    uint32_t r;
    asm("cvt.rn.satfinite.bf16x2.f32 %0, %1, %2;" : "=r"(r) : "f"(f_odd), "f"(f_even));
    return r;
}
__device__ __forceinline__ void split_pair(float fe, float fo, uint32_t& hi, uint32_t& lo) {
    hi = pack_bf16x2(fe, fo);
    float he = __uint_as_float(hi << 16);
    float ho = __uint_as_float(hi & 0xFFFF0000u);
    lo = pack_bf16x2(fe - he, fo - ho);
}
__device__ __forceinline__ void store_split4(uint32_t* XH, uint32_t* XL, size_t idx, float4 v) {
    uint32_t h0, l0, h1, l1;
    split_pair(v.x, v.y, h0, l0);
    split_pair(v.z, v.w, h1, l1);
    *(uint2*)(XH + idx) = make_uint2(h0, h1);
    *(uint2*)(XL + idx) = make_uint2(l0, l1);
}

// ---------------- utility ---------------------------------------------------
__global__ void k_zero_f(float* __restrict__ p, int n) {
    int t = blockIdx.x * blockDim.x + threadIdx.x;
    if (t < n) p[t] = 0.f;
}
__global__ void k_zero_i(int* __restrict__ p, int n) {
    int t = blockIdx.x * blockDim.x + threadIdx.x;
    if (t < n) p[t] = 0;
}

// ---------------- CSR build -------------------------------------------------
__global__ void k_count(const int* __restrict__ dst) {
    int t = blockIdx.x * blockDim.x + threadIdx.x;
    if (t < NE) atomicAdd(&g_cnt[dst[t]], 1);
}
__global__ void k_scan1() {
    __shared__ int sh[512];
    int b = blockIdx.x, t = threadIdx.x, i = b * 512 + t;
    int v = (i < NP) ? g_cnt[i] : 0;
    sh[t] = v;
    __syncthreads();
#pragma unroll
    for (int o = 1; o < 512; o <<= 1) {
        int x = (t >= o) ? sh[t - o] : 0;
        __syncthreads();
        sh[t] += x;
        __syncthreads();
    }
    if (i < NP) g_base[i + 1] = sh[t];
    if (t == 511) g_bsum[b] = sh[511];
}
__global__ void k_scan2() {
    if (threadIdx.x == 0) {
        int s = 0;
        for (int b = 0; b < NB; b++) { int c = g_bsum[b]; g_bsum[b] = s; s += c; }
    }
}
__global__ void k_scan3() {
    int i = blockIdx.x * blockDim.x + threadIdx.x;
    if (i < NP) g_base[i + 1] += g_bsum[i >> 9];
    if (i == 0) g_base[0] = 0;
}
__global__ void k_fill(const int* __restrict__ src, const int* __restrict__ dst) {
    int t = blockIdx.x * blockDim.x + threadIdx.x;
    if (t >= NE) return;
    int d = dst[t];
    int p = g_base[d] + atomicAdd(&g_fill[d], 1);
    g_src[p] = src[t];
    g_eid[p] = t;
}

// ---------------- edge-feature gather-sum per dst node ----------------------
__global__ void k_gather_e(const float* __restrict__ ef) {
    int w = (blockIdx.x * blockDim.x + threadIdx.x) >> 5;
    int lane = threadIdx.x & 31;
    if (w >= NN || lane >= 16) return;
    int e0 = g_base[w], e1 = g_base[w + 1];
    float4 a = {0.f, 0.f, 0.f, 0.f};
    for (int e = e0; e < e1; e++) {
        int id = g_eid[e];
        float4 v = *(const float4*)(ef + (size_t)id * ED + lane * 4);
        a.x += v.x; a.y += v.y; a.z += v.z; a.w += v.w;
    }
    *(float4*)(g_eagg + (size_t)w * ED + lane * 4) = a;
}

// ---------------- static pair columns (split, once per launch) ---------------
// pairs per row v: [0,FP2)=x | [FP2,2FP2)=mean | [2FP2,2FP2+32)=inv*eagg
//                  pair 2FP2+32 = (indicator,0) | rest zero ; pad rows all zero
template <int PK2, int FP2>
__global__ void k_static_s(uint32_t* __restrict__ XH, uint32_t* __restrict__ XL) {
    int t = blockIdx.x * blockDim.x + threadIdx.x;
    if (t >= NP * PK2) return;
    int v = t / PK2, p = t - v * PK2;
    if (v >= NN) { XH[t] = 0u; XL[t] = 0u; return; }
    if (p < 2 * FP2) return;                  // dynamic, written per layer
    int dg = g_cnt[v];
    float f0 = 0.f, f1 = 0.f;
    if (p < 2 * FP2 + 32) {
        float inv = 1.f / (float)max(dg, 1);
        int c = (p - 2 * FP2) * 2;
        f0 = inv * g_eagg[(size_t)v * ED + c];
        f1 = inv * g_eagg[(size_t)v * ED + c + 1];
    } else if (p == 2 * FP2 + 32) {
        f0 = (dg > 0) ? 1.f : 0.f;
    }
    uint32_t h, l;
    split_pair(f0, f1, h, l);
    XH[t] = h; XL[t] = l;
}

// ---------------- per-layer gather: self + mean, written split --------------
template <int NC4, int PK2>
__global__ void k_gather_s(const float* __restrict__ X, int ldx,
                           uint32_t* __restrict__ XH, uint32_t* __restrict__ XL) {
    int w = (blockIdx.x * blockDim.x + threadIdx.x) >> 5;
    int lane = threadIdx.x & 31;
    if (w >= NN) return;
    int e0 = g_base[w], e1 = g_base[w + 1];
    int c0 = lane, c1 = lane + 32;
    float4 a0 = {0.f, 0.f, 0.f, 0.f};
    float4 a1 = {0.f, 0.f, 0.f, 0.f};
    for (int e = e0; e < e1; e++) {
        int s = g_src[e];
        const float4* row = (const float4*)(X + (size_t)s * ldx);
        if (c0 < NC4) {
            float4 v = row[c0];
            a0.x += v.x; a0.y += v.y; a0.z += v.z; a0.w += v.w;
        }
        if (NC4 > 32 && c1 < NC4) {
            float4 v = row[c1];
            a1.x += v.x; a1.y += v.y; a1.z += v.z; a1.w += v.w;
        }
    }
    float inv = 1.f / fmaxf((float)(e1 - e0), 1.f);
    const float4* xrow = (const float4*)(X + (size_t)w * ldx);
    size_t rb = (size_t)w * PK2;
    if (c0 < NC4) {
        store_split4(XH, XL, rb + 2 * c0, xrow[c0]);
        float4 r; r.x = a0.x * inv; r.y = a0.y * inv; r.z = a0.z * inv; r.w = a0.w * inv;
        store_split4(XH, XL, rb + 2 * NC4 + 2 * c0, r);
    }
    if (NC4 > 32 && c1 < NC4) {
        store_split4(XH, XL, rb + 2 * c1, xrow[c1]);
        float4 r; r.x = a1.x * inv; r.y = a1.y * inv; r.z = a1.z * inv; r.w = a1.w * inv;
        store_split4(XH, XL, rb + 2 * NC4 + 2 * c1, r);
    }
}

// ---------------- build fused weight Wc (float intermediate) ----------------
__global__ void k_wc(const float* __restrict__ Wm, const float* __restrict__ bm,
                     const float* __restrict__ Wa, float* __restrict__ Wc,
                     int Fin, int Fm, int Fout, int Kp) {
    int col = blockIdx.x * blockDim.x + threadIdx.x;
    int j = blockIdx.y;
    int K1 = 2 * Fin + ED + 1;
    if (col >= K1 || j >= Fout) return;
    int WmK = Fin + ED;
    int WaK = Fin + Fm;
    const float* wah = Wa + (size_t)j * WaK + Fin;
    float val;
    if (col < Fin) {
        val = Wa[(size_t)j * WaK + col];
    } else if (col < 2 * Fin) {
        int i = col - Fin;
        float s = 0.f;
        for (int t = 0; t < Fm; t++) s += wah[t] * Wm[(size_t)t * WmK + i];
        val = s;
    } else if (col < 2 * Fin + ED) {
        int i = col - 2 * Fin;
        float s = 0.f;
        for (int t = 0; t < Fm; t++) s += wah[t] * Wm[(size_t)t * WmK + Fin + i];
        val = s;
    } else {
        float s = 0.f;
        for (int t = 0; t < Fm; t++) s += wah[t] * bm[t];
        val = s;
    }
    Wc[(size_t)j * Kp + col] = val;
}

// ---------------- split float weight rows -> hi/lo bf16x2 pairs --------------
__global__ void k_split(const float* __restrict__ W, uint32_t* __restrict__ WH,
                        uint32_t* __restrict__ WL, int rows, int kp_f, int pk2) {
    int t = blockIdx.x * blockDim.x + threadIdx.x;
    if (t >= rows * pk2) return;
    int r = t / pk2, p = t - r * pk2;
    float f0 = (2 * p     < kp_f) ? W[(size_t)r * kp_f + 2 * p]     : 0.f;
    float f1 = (2 * p + 1 < kp_f) ? W[(size_t)r * kp_f + 2 * p + 1] : 0.f;
    uint32_t h, l;
    split_pair(f0, f1, h, l);
    WH[t] = h; WL[t] = l;
}

// ---------------- bf16x3 GEMM on pre-split inputs ---------------------------
// C = relu(A @ B^T + bias). BM=128, BN=64, BK=32 (16 pairs); 256 threads,
// 8 warps 4(m)x2(n), warp tile 32x32. Inner loop: scalar LDS + mma only.
__device__ __forceinline__ void mma_bf16(float* c, const uint32_t* a, const uint32_t* b) {
    asm volatile(
        "mma.sync.aligned.m16n8k16.row.col.f32.bf16.bf16.f32 "
        "{%0,%1,%2,%3}, {%4,%5,%6,%7}, {%8,%9}, {%0,%1,%2,%3};"
        : "+f"(c[0]), "+f"(c[1]), "+f"(c[2]), "+f"(c[3])
        : "r"(a[0]), "r"(a[1]), "r"(a[2]), "r"(a[3]), "r"(b[0]), "r"(b[1]));
}

__global__ __launch_bounds__(256) void k_gemm_s(
    const uint32_t* __restrict__ AH, const uint32_t* __restrict__ AL,
    const uint32_t* __restrict__ BH, const uint32_t* __restrict__ BL,
    const float* __restrict__ bias, float* __restrict__ C,
    int M, int Nout, int PK2, int ldc) {
    // [row][pair] pitch 20: frag LDS bank = (20g+t4) mod 32 all-distinct;
    // 16B-aligned uint4 STS. smem = (128+64)*20*4*2 = 30720 B.
    __shared__ uint32_t sAH[128][20], sAL[128][20];
    __shared__ uint32_t sBH[64][20],  sBL[64][20];
    const int m0 = blockIdx.x * 128;
    const int n0 = blockIdx.y * 64;
    const int tid = threadIdx.x;
    const int lane = tid & 31, wid = tid >> 5;
    const int mw = wid >> 1, nw = wid & 1;
    const int g = lane >> 2, t4 = lane & 3;

    // staging assignments (STS bank-conflict-free: rows advance with lane)
    const int ar = tid & 127, ac = (tid >> 7) * 8;       // A: row ar, pairs ac..ac+7
    const int br = tid & 63,  bc = ((tid >> 6) & 3) * 4; // B: row br, pairs bc..bc+3

    float acc[2][4][4];
#pragma unroll
    for (int i = 0; i < 2; i++)
#pragma unroll
        for (int j = 0; j < 4; j++)
#pragma unroll
            for (int e = 0; e < 4; e++) acc[i][j][e] = 0.f;

    for (int kp0 = 0; kp0 < PK2; kp0 += 16) {
        const uint32_t* gAh = AH + (size_t)(m0 + ar) * PK2 + kp0 + ac;
        const uint32_t* gAl = AL + (size_t)(m0 + ar) * PK2 + kp0 + ac;
        uint4 vh0 = *(const uint4*)gAh;
        uint4 vh1 = *(const uint4*)(gAh + 4);
        uint4 vl0 = *(const uint4*)gAl;
        uint4 vl1 = *(const uint4*)(gAl + 4);
        uint4 wh = *(const uint4*)(BH + (size_t)(n0 + br) * PK2 + kp0 + bc);
        uint4 wl = *(const uint4*)(BL + (size_t)(n0 + br) * PK2 + kp0 + bc);
        __syncthreads();   // previous iter fully consumed
        *(uint4*)&sAH[ar][ac]     = vh0;
        *(uint4*)&sAH[ar][ac + 4] = vh1;
        *(uint4*)&sAL[ar][ac]     = vl0;
        *(uint4*)&sAL[ar][ac + 4] = vl1;
        *(uint4*)&sBH[br][bc] = wh;
        *(uint4*)&sBL[br][bc] = wl;
        __syncthreads();

#pragma unroll
        for (int ks = 0; ks < 2; ks++) {
            const int kb = ks * 8;
            uint32_t ah[2][4], al[2][4], bh[4][2], bl[4][2];
#pragma unroll
            for (int j = 0; j < 4; j++) {
                int nn = nw * 32 + j * 8 + g;
                bh[j][0] = sBH[nn][kb + t4];     bl[j][0] = sBL[nn][kb + t4];
                bh[j][1] = sBH[nn][kb + t4 + 4]; bl[j][1] = sBL[nn][kb + t4 + 4];
            }
#pragma unroll
            for (int i = 0; i < 2; i++) {
                int rr = mw * 32 + i * 16 + g;
                ah[i][0] = sAH[rr][kb + t4];         al[i][0] = sAL[rr][kb + t4];
                ah[i][1] = sAH[rr + 8][kb + t4];     al[i][1] = sAL[rr + 8][kb + t4];
                ah[i][2] = sAH[rr][kb + t4 + 4];     al[i][2] = sAL[rr][kb + t4 + 4];
                ah[i][3] = sAH[rr + 8][kb + t4 + 4]; al[i][3] = sAL[rr + 8][kb + t4 + 4];
            }
#pragma unroll
            for (int i = 0; i < 2; i++)
#pragma unroll
                for (int j = 0; j < 4; j++) {
                    mma_bf16(acc[i][j], ah[i], bh[j]);
                    mma_bf16(acc[i][j], al[i], bh[j]);
                    mma_bf16(acc[i][j], ah[i], bl[j]);
                }
        }
    }

    // epilogue: bias + relu
#pragma unroll
    for (int i = 0; i < 2; i++) {
#pragma unroll
        for (int j = 0; j < 4; j++) {
            int ncol = n0 + nw * 32 + j * 8 + 2 * t4;
            if (ncol >= Nout) continue;            // Nout multiple of 8: pair safe
            float b0 = bias[ncol], b1 = bias[ncol + 1];
            int mrow = m0 + mw * 32 + i * 16 + g;
            if (mrow < M) {
                float2 r0 = {fmaxf(acc[i][j][0] + b0, 0.f), fmaxf(acc[i][j][1] + b1, 0.f)};
                *(float2*)(C + (size_t)mrow * ldc + ncol) = r0;
            }
            if (mrow + 8 < M) {
                float2 r1 = {fmaxf(acc[i][j][2] + b0, 0.f), fmaxf(acc[i][j][3] + b1, 0.f)};
                *(float2*)(C + (size_t)(mrow + 8) * ldc + ncol) = r1;
            }
        }
    }
}

// ---------------- driver ----------------------------------------------------
extern "C" void kernel_launch(void* const* d_in, const int* in_sizes, int n_in,
                              void* d_out, int out_size) {
    const float* nf  = (const float*)d_in[0];
    const float* ef  = (const float*)d_in[1];
    const float* Wm1 = (const float*)d_in[2];  const float* bm1 = (const float*)d_in[3];
    const float* Wa1 = (const float*)d_in[4];  const float* ba1 = (const float*)d_in[5];
    const float* Wm2 = (const float*)d_in[6];  const float* bm2 = (const float*)d_in[7];
    const float* Wa2 = (const float*)d_in[8];  const float* ba2 = (const float*)d_in[9];
    const float* Wm3 = (const float*)d_in[10]; const float* bm3 = (const float*)d_in[11];
    const float* Wa3 = (const float*)d_in[12]; const float* ba3 = (const float*)d_in[13];
    const int* src = (const int*)d_in[14];
    const int* dst = (const int*)d_in[15];
    float* out = (float*)d_out;

    float *p_h1, *p_h2, *p_wc1, *p_wc2, *p_wc3;
    int *p_cnt, *p_fill;
    uint32_t *p_xh1, *p_xl1, *p_xh2, *p_xl2;
    uint32_t *p_wh1, *p_wl1, *p_wh2, *p_wl2, *p_wh3, *p_wl3;
    cudaGetSymbolAddress((void**)&p_cnt,  g_cnt);
    cudaGetSymbolAddress((void**)&p_fill, g_fill);
    cudaGetSymbolAddress((void**)&p_h1,   g_h1);
    cudaGetSymbolAddress((void**)&p_h2,   g_h2);
    cudaGetSymbolAddress((void**)&p_wc1,  g_wc1);
    cudaGetSymbolAddress((void**)&p_wc2,  g_wc2);
    cudaGetSymbolAddress((void**)&p_wc3,  g_wc3);
    cudaGetSymbolAddress((void**)&p_xh1,  g_xh1);
    cudaGetSymbolAddress((void**)&p_xl1,  g_xl1);
    cudaGetSymbolAddress((void**)&p_xh2,  g_xh2);
    cudaGetSymbolAddress((void**)&p_xl2,  g_xl2);
    cudaGetSymbolAddress((void**)&p_wh1,  g_wh1);
    cudaGetSymbolAddress((void**)&p_wl1,  g_wl1);
    cudaGetSymbolAddress((void**)&p_wh2,  g_wh2);
    cudaGetSymbolAddress((void**)&p_wl2,  g_wl2);
    cudaGetSymbolAddress((void**)&p_wh3,  g_wh3);
    cudaGetSymbolAddress((void**)&p_wl3,  g_wl3);

    const int GW = (NN * 32 + 255) / 256;   // warp-per-node grids

    // ---- CSR build ----
    k_zero_i<<<(NP + 255) / 256, 256>>>(p_cnt, NP);
    k_zero_i<<<(NP + 255) / 256, 256>>>(p_fill, NP);
    k_count<<<(NE + 255) / 256, 256>>>(dst);
    k_scan1<<<NB, 512>>>();
    k_scan2<<<1, 32>>>();
    k_scan3<<<(NP + 255) / 256, 256>>>();
    k_fill<<<(NE + 255) / 256, 256>>>(src, dst);

    // ---- graph-constant: edge agg + static split columns ----
    k_gather_e<<<GW, 256>>>(ef);
    k_static_s<PK2_1, 32><<<(NP * PK2_1 + 255) / 256, 256>>>(p_xh1, p_xl1);
    k_static_s<PK2_2, 76><<<(NP * PK2_2 + 255) / 256, 256>>>(p_xh2, p_xl2);

    // ---- fused weights (float) then split ----
    k_zero_f<<<(192 * 224 + 255) / 256, 256>>>(p_wc1, 192 * 224);
    k_zero_f<<<(192 * 384 + 255) / 256, 256>>>(p_wc2, 192 * 384);
    k_zero_f<<<(64 * 384 + 255) / 256, 256>>>(p_wc3, 64 * 384);
    k_wc<<<dim3(2, 152), 128>>>(Wm1, bm1, Wa1, p_wc1, 64, 152, 152, 224);
    k_wc<<<dim3(3, 152), 128>>>(Wm2, bm2, Wa2, p_wc2, 152, 152, 152, 384);
    k_wc<<<dim3(3, 64), 128>>>(Wm3, bm3, Wa3, p_wc3, 152, 64, 64, 384);
    k_split<<<(192 * PK2_1 + 255) / 256, 256>>>(p_wc1, p_wh1, p_wl1, 192, 224, PK2_1);
    k_split<<<(192 * PK2_2 + 255) / 256, 256>>>(p_wc2, p_wh2, p_wl2, 192, 384, PK2_2);
    k_split<<<(64 * PK2_2 + 255) / 256, 256>>>(p_wc3, p_wh3, p_wl3, 64, 384, PK2_2);

    // ---- layer 1 (64 -> 152) ----
    k_gather_s<16, PK2_1><<<GW, 256>>>(nf, 64, p_xh1, p_xl1);
    k_gemm_s<<<dim3(NP / 128, 3), 256>>>(p_xh1, p_xl1, p_wh1, p_wl1, ba1, p_h1,
                                         NN, 152, PK2_1, HID);

    // ---- layer 2 (152 -> 152) ----
    k_gather_s<38, PK2_2><<<GW, 256>>>(p_h1, HID, p_xh2, p_xl2);
    k_gemm_s<<<dim3(NP / 128, 3), 256>>>(p_xh2, p_xl2, p_wh2, p_wl2, ba2, p_h2,
                                         NN, 152, PK2_2, HID);

    // ---- layer 3 (152 -> 64) ----
    k_gather_s<38, PK2_2><<<GW, 256>>>(p_h2, HID, p_xh2, p_xl2);
    k_gemm_s<<<dim3(NP / 128, 1), 256>>>(p_xh2, p_xl2, p_wh3, p_wl3, ba3, out,
                                         NN, 64, PK2_2, 64);
}

// round 13
// speedup vs baseline: 1.1334x; 1.1334x over previous
#include <cuda_runtime.h>
#include <cstdint>

#define NN 50000      // nodes
#define NE 800000     // edges
#define NP 50048      // nodes padded to multiple of 128
#define NB 98         // scan blocks: ceil(NP/512)
#define ED 64         // edge feature dim
#define HID 152

// ---------------- scratch (device globals; no allocation allowed) ----------
__device__ int   g_cnt[NP];
__device__ int   g_fill[NP];
__device__ int   g_base[NP + 1];
__device__ int   g_bsum[128];
__device__ int   g_src[NE];      // src node per edge, CSR-ordered by dst
__device__ int   g_eid[NE];      // original edge id, CSR-ordered by dst
__device__ float g_eagg[(size_t)NP * ED];
__device__ float g_h1[(size_t)NP * HID];
__device__ float g_h2[(size_t)NP * HID];
__device__ float g_xc1[(size_t)NP * 208];
__device__ float g_xc2[(size_t)NP * 384];
__device__ float g_wc1[192 * 208];
__device__ float g_wc2[192 * 384];
__device__ float g_wc3[64 * 384];

// ---------------- utility ---------------------------------------------------
__global__ void k_zero_f(float* __restrict__ p, int n) {
    int t = blockIdx.x * blockDim.x + threadIdx.x;
    if (t < n) p[t] = 0.f;
}
__global__ void k_zero_i(int* __restrict__ p, int n) {
    int t = blockIdx.x * blockDim.x + threadIdx.x;
    if (t < n) p[t] = 0;
}

// ---------------- CSR build -------------------------------------------------
__global__ void k_count(const int* __restrict__ dst) {
    int t = blockIdx.x * blockDim.x + threadIdx.x;
    if (t < NE) atomicAdd(&g_cnt[dst[t]], 1);
}
__global__ void k_scan1() {
    __shared__ int sh[512];
    int b = blockIdx.x, t = threadIdx.x, i = b * 512 + t;
    int v = (i < NP) ? g_cnt[i] : 0;
    sh[t] = v;
    __syncthreads();
#pragma unroll
    for (int o = 1; o < 512; o <<= 1) {
        int x = (t >= o) ? sh[t - o] : 0;
        __syncthreads();
        sh[t] += x;
        __syncthreads();
    }
    if (i < NP) g_base[i + 1] = sh[t];
    if (t == 511) g_bsum[b] = sh[511];
}
__global__ void k_scan2() {
    if (threadIdx.x == 0) {
        int s = 0;
        for (int b = 0; b < NB; b++) { int c = g_bsum[b]; g_bsum[b] = s; s += c; }
    }
}
__global__ void k_scan3() {
    int i = blockIdx.x * blockDim.x + threadIdx.x;
    if (i < NP) g_base[i + 1] += g_bsum[i >> 9];
    if (i == 0) g_base[0] = 0;
}
__global__ void k_fill(const int* __restrict__ src, const int* __restrict__ dst) {
    int t = blockIdx.x * blockDim.x + threadIdx.x;
    if (t >= NE) return;
    int d = dst[t];
    int p = g_base[d] + atomicAdd(&g_fill[d], 1);
    g_src[p] = src[t];
    g_eid[p] = t;
}

// ---------------- edge-feature gather-sum per dst node ----------------------
__global__ void k_gather_e(const float* __restrict__ ef) {
    int w = (blockIdx.x * blockDim.x + threadIdx.x) >> 5;
    int lane = threadIdx.x & 31;
    if (w >= NN || lane >= 16) return;
    int e0 = g_base[w], e1 = g_base[w + 1];
    float4 a = {0.f, 0.f, 0.f, 0.f};
    for (int e = e0; e < e1; e++) {
        int id = g_eid[e];
        float4 v = *(const float4*)(ef + (size_t)id * ED + lane * 4);
        a.x += v.x; a.y += v.y; a.z += v.z; a.w += v.w;
    }
    *(float4*)(g_eagg + (size_t)w * ED + lane * 4) = a;
}

// ---------------- static columns of fused GEMM input (once per launch) ------
// layout per row v: [0,FIN)=x  [FIN,2FIN)=inv*na  [2FIN,2FIN+64)=inv*eagg
//                   [2FIN+64]=indicator  rest=0 ; pad rows fully 0
template <int KP, int FIN>
__global__ void k_static(float* __restrict__ XC) {
    int t = blockIdx.x * blockDim.x + threadIdx.x;
    if (t >= NP * KP) return;
    int v = t / KP, col = t - v * KP;
    float* p = XC + (size_t)v * KP + col;
    if (v >= NN) { *p = 0.f; return; }
    if (col < 2 * FIN) return;                 // dynamic: written by gather each layer
    int dg = g_cnt[v];
    float val = 0.f;
    if (col < 2 * FIN + 64) {
        float inv = 1.f / (float)max(dg, 1);
        val = inv * g_eagg[(size_t)v * ED + (col - 2 * FIN)];
    } else if (col == 2 * FIN + 64) {
        val = (dg > 0) ? 1.f : 0.f;
    }
    *p = val;
}

// ---------------- per-layer: copy x + gather mean of src rows into XC -------
template <int NC4, int FIN, int KP>
__global__ void k_gather(const float* __restrict__ X, int ldx, float* __restrict__ XC) {
    int w = (blockIdx.x * blockDim.x + threadIdx.x) >> 5;
    int lane = threadIdx.x & 31;
    if (w >= NN) return;
    int e0 = g_base[w], e1 = g_base[w + 1];
    int c0 = lane, c1 = lane + 32;
    float4 a0 = {0.f, 0.f, 0.f, 0.f};
    float4 a1 = {0.f, 0.f, 0.f, 0.f};
    for (int e = e0; e < e1; e++) {
        int s = g_src[e];
        const float4* row = (const float4*)(X + (size_t)s * ldx);
        if (c0 < NC4) {
            float4 v = row[c0];
            a0.x += v.x; a0.y += v.y; a0.z += v.z; a0.w += v.w;
        }
        if (NC4 > 32 && c1 < NC4) {
            float4 v = row[c1];
            a1.x += v.x; a1.y += v.y; a1.z += v.z; a1.w += v.w;
        }
    }
    float inv = 1.f / fmaxf((float)(e1 - e0), 1.f);
    float4* out = (float4*)(XC + (size_t)w * KP);
    const float4* xrow = (const float4*)(X + (size_t)w * ldx);
    if (c0 < NC4) {
        out[c0] = xrow[c0];
        float4 r; r.x = a0.x * inv; r.y = a0.y * inv; r.z = a0.z * inv; r.w = a0.w * inv;
        out[FIN / 4 + c0] = r;
    }
    if (NC4 > 32 && c1 < NC4) {
        out[c1] = xrow[c1];
        float4 r; r.x = a1.x * inv; r.y = a1.y * inv; r.z = a1.z * inv; r.w = a1.w * inv;
        out[FIN / 4 + c1] = r;
    }
}

// ---------------- build fused weight Wc = [Wa_self | Wa_h@Wm_n | Wa_h@Wm_e | Wa_h@bm]
__global__ void k_wc(const float* __restrict__ Wm, const float* __restrict__ bm,
                     const float* __restrict__ Wa, float* __restrict__ Wc,
                     int Fin, int Fm, int Fout, int Kp) {
    int col = blockIdx.x * blockDim.x + threadIdx.x;
    int j = blockIdx.y;
    int K1 = 2 * Fin + ED + 1;
    if (col >= K1 || j >= Fout) return;
    int WmK = Fin + ED;
    int WaK = Fin + Fm;
    const float* wah = Wa + (size_t)j * WaK + Fin;
    float val;
    if (col < Fin) {
        val = Wa[(size_t)j * WaK + col];
    } else if (col < 2 * Fin) {
        int i = col - Fin;
        float s = 0.f;
        for (int t = 0; t < Fm; t++) s += wah[t] * Wm[(size_t)t * WmK + i];
        val = s;
    } else if (col < 2 * Fin + ED) {
        int i = col - 2 * Fin;
        float s = 0.f;
        for (int t = 0; t < Fm; t++) s += wah[t] * Wm[(size_t)t * WmK + Fin + i];
        val = s;
    } else {
        float s = 0.f;
        for (int t = 0; t < Fm; t++) s += wah[t] * bm[t];
        val = s;
    }
    Wc[(size_t)j * Kp + col] = val;
}

// ---------------- bf16x3 tensor-core GEMM, double-buffered ------------------
// C = relu(Xc @ Wc^T + bias). BM=128, BN=64, BK=16; 256 threads, 8 warps
// 4(m)x2(n), warp tile 32x32. Split to bf16 hi/lo AT STAGING (R11 structure);
// 2-stage smem pipeline so next tile's GLDs overlap current tile's MMAs.

__device__ __forceinline__ uint32_t pack_bf16x2(float f_even, float f_odd) {
    uint32_t r;
    asm("cvt.rn.satfinite.bf16x2.f32 %0, %1, %2;" : "=r"(r) : "f"(f_odd), "f"(f_even));
    return r;
}
__device__ __forceinline__ void split_pair(float fe, float fo, uint32_t& hi, uint32_t& lo) {
    hi = pack_bf16x2(fe, fo);
    float he = __uint_as_float(hi << 16);
    float ho = __uint_as_float(hi & 0xFFFF0000u);
    lo = pack_bf16x2(fe - he, fo - ho);
}
__device__ __forceinline__ void mma_bf16(float* c, const uint32_t* a, const uint32_t* b) {
    asm volatile(
        "mma.sync.aligned.m16n8k16.row.col.f32.bf16.bf16.f32 "
        "{%0,%1,%2,%3}, {%4,%5,%6,%7}, {%8,%9}, {%0,%1,%2,%3};"
        : "+f"(c[0]), "+f"(c[1]), "+f"(c[2]), "+f"(c[3])
        : "r"(a[0]), "r"(a[1]), "r"(a[2]), "r"(a[3]), "r"(b[0]), "r"(b[1]));
}

__global__ __launch_bounds__(256) void k_gemm_bf(
    const float* __restrict__ A, const float* __restrict__ B,
    const float* __restrict__ bias, float* __restrict__ C,
    int M, int Nout, int Kp, int ldc) {
    // strides conflict-free for fragment loads (proven in R11):
    // A: bank = 8*t4+g bijective; B: bank = 12*g+t4 all-distinct
    __shared__ uint32_t Ahi[2][8][136], Alo[2][8][136];
    __shared__ uint32_t Bhi[2][64][12], Blo[2][64][12];
    const int m0 = blockIdx.x * 128;
    const int n0 = blockIdx.y * 64;
    const int tid = threadIdx.x;
    const int lane = tid & 31, wid = tid >> 5;
    const int mw = wid >> 1, nw = wid & 1;     // 4 x 2 warp grid
    const int g = lane >> 2, t4 = lane & 3;

    float acc[2][4][4];
#pragma unroll
    for (int i = 0; i < 2; i++)
#pragma unroll
        for (int j = 0; j < 4; j++)
#pragma unroll
            for (int e = 0; e < 4; e++) acc[i][j][e] = 0.f;

    float4 va[2], vb;

    // tile loaders / split-stores (register-staged; split amortized once per elem)
    auto load_tiles = [&](int k0) {
#pragma unroll
        for (int i = 0; i < 2; i++) {
            int idx = tid + i * 256;
            int r = idx >> 2, kq = (idx & 3) << 2;
            va[i] = *(const float4*)(A + (size_t)(m0 + r) * Kp + (k0 + kq));
        }
        int r = tid >> 2, kq = (tid & 3) << 2;
        vb = *(const float4*)(B + (size_t)(n0 + r) * Kp + (k0 + kq));
    };
    auto store_tiles = [&](int bsel) {
#pragma unroll
        for (int i = 0; i < 2; i++) {
            int idx = tid + i * 256;
            int r = idx >> 2, kp = (idx & 3) << 1;
            split_pair(va[i].x, va[i].y, Ahi[bsel][kp][r],     Alo[bsel][kp][r]);
            split_pair(va[i].z, va[i].w, Ahi[bsel][kp + 1][r], Alo[bsel][kp + 1][r]);
        }
        int r = tid >> 2, kp = (tid & 3) << 1;
        split_pair(vb.x, vb.y, Bhi[bsel][r][kp],     Blo[bsel][r][kp]);
        split_pair(vb.z, vb.w, Bhi[bsel][r][kp + 1], Blo[bsel][r][kp + 1]);
    };
    auto compute = [&](int bsel) {
        uint32_t ah[2][4], al[2][4], bh[4][2], bl[4][2];
#pragma unroll
        for (int j = 0; j < 4; j++) {
            int nn = nw * 32 + j * 8 + g;
            bh[j][0] = Bhi[bsel][nn][t4];     bl[j][0] = Blo[bsel][nn][t4];
            bh[j][1] = Bhi[bsel][nn][t4 + 4]; bl[j][1] = Blo[bsel][nn][t4 + 4];
        }
#pragma unroll
        for (int i = 0; i < 2; i++) {
            int rr = mw * 32 + i * 16 + g;
            ah[i][0] = Ahi[bsel][t4][rr];     al[i][0] = Alo[bsel][t4][rr];
            ah[i][1] = Ahi[bsel][t4][rr + 8]; al[i][1] = Alo[bsel][t4][rr + 8];
            ah[i][2] = Ahi[bsel][t4 + 4][rr];     al[i][2] = Alo[bsel][t4 + 4][rr];
            ah[i][3] = Ahi[bsel][t4 + 4][rr + 8]; al[i][3] = Alo[bsel][t4 + 4][rr + 8];
        }
#pragma unroll
        for (int i = 0; i < 2; i++)
#pragma unroll
            for (int j = 0; j < 4; j++) {
                mma_bf16(acc[i][j], ah[i], bh[j]);
                mma_bf16(acc[i][j], al[i], bh[j]);
                mma_bf16(acc[i][j], ah[i], bl[j]);
            }
    };

    // prologue: fill stage 0
    load_tiles(0);
    store_tiles(0);
    __syncthreads();

    int buf = 0;
    for (int k0 = 16; k0 < Kp; k0 += 16) {
        load_tiles(k0);        // GLDs in flight while we compute the current tile
        compute(buf);          // consume smem[buf]
        store_tiles(buf ^ 1);  // stage next tile (waits on GLDs, hidden by MMAs)
        __syncthreads();       // release: reads of buf done; writes of buf^1 visible
        buf ^= 1;
    }
    compute(buf);

    // epilogue: bias + relu
#pragma unroll
    for (int i = 0; i < 2; i++) {
#pragma unroll
        for (int j = 0; j < 4; j++) {
            int ncol = n0 + nw * 32 + j * 8 + 2 * t4;
            if (ncol >= Nout) continue;            // Nout multiple of 8: pair safe
            float b0 = bias[ncol], b1 = bias[ncol + 1];
            int mrow = m0 + mw * 32 + i * 16 + g;
            if (mrow < M) {
                float2 r0 = {fmaxf(acc[i][j][0] + b0, 0.f), fmaxf(acc[i][j][1] + b1, 0.f)};
                *(float2*)(C + (size_t)mrow * ldc + ncol) = r0;
            }
            if (mrow + 8 < M) {
                float2 r1 = {fmaxf(acc[i][j][2] + b0, 0.f), fmaxf(acc[i][j][3] + b1, 0.f)};
                *(float2*)(C + (size_t)(mrow + 8) * ldc + ncol) = r1;
            }
        }
    }
}

// ---------------- driver ----------------------------------------------------
extern "C" void kernel_launch(void* const* d_in, const int* in_sizes, int n_in,
                              void* d_out, int out_size) {
    const float* nf  = (const float*)d_in[0];
    const float* ef  = (const float*)d_in[1];
    const float* Wm1 = (const float*)d_in[2];  const float* bm1 = (const float*)d_in[3];
    const float* Wa1 = (const float*)d_in[4];  const float* ba1 = (const float*)d_in[5];
    const float* Wm2 = (const float*)d_in[6];  const float* bm2 = (const float*)d_in[7];
    const float* Wa2 = (const float*)d_in[8];  const float* ba2 = (const float*)d_in[9];
    const float* Wm3 = (const float*)d_in[10]; const float* bm3 = (const float*)d_in[11];
    const float* Wa3 = (const float*)d_in[12]; const float* ba3 = (const float*)d_in[13];
    const int* src = (const int*)d_in[14];
    const int* dst = (const int*)d_in[15];
    float* out = (float*)d_out;

    float *p_h1, *p_h2, *p_xc1, *p_xc2, *p_wc1, *p_wc2, *p_wc3;
    int *p_cnt, *p_fill;
    cudaGetSymbolAddress((void**)&p_cnt,  g_cnt);
    cudaGetSymbolAddress((void**)&p_fill, g_fill);
    cudaGetSymbolAddress((void**)&p_h1,   g_h1);
    cudaGetSymbolAddress((void**)&p_h2,   g_h2);
    cudaGetSymbolAddress((void**)&p_xc1,  g_xc1);
    cudaGetSymbolAddress((void**)&p_xc2,  g_xc2);
    cudaGetSymbolAddress((void**)&p_wc1,  g_wc1);
    cudaGetSymbolAddress((void**)&p_wc2,  g_wc2);
    cudaGetSymbolAddress((void**)&p_wc3,  g_wc3);

    const int GW = (NN * 32 + 255) / 256;   // warp-per-node grids

    // ---- CSR build (int atomics only; ~2.4M ops) ----
    k_zero_i<<<(NP + 255) / 256, 256>>>(p_cnt, NP);
    k_zero_i<<<(NP + 255) / 256, 256>>>(p_fill, NP);
    k_count<<<(NE + 255) / 256, 256>>>(dst);
    k_scan1<<<NB, 512>>>();
    k_scan2<<<1, 32>>>();
    k_scan3<<<(NP + 255) / 256, 256>>>();
    k_fill<<<(NE + 255) / 256, 256>>>(src, dst);

    // ---- graph-constant: edge-feature aggregation + static Xc columns ----
    k_gather_e<<<GW, 256>>>(ef);
    k_static<208,  64><<<(NP * 208 + 255) / 256, 256>>>(p_xc1);
    k_static<384, 152><<<(NP * 384 + 255) / 256, 256>>>(p_xc2);

    // ---- fused weights ----
    k_zero_f<<<(192 * 208 + 255) / 256, 256>>>(p_wc1, 192 * 208);
    k_zero_f<<<(192 * 384 + 255) / 256, 256>>>(p_wc2, 192 * 384);
    k_zero_f<<<(64 * 384 + 255) / 256, 256>>>(p_wc3, 64 * 384);
    k_wc<<<dim3(2, 152), 128>>>(Wm1, bm1, Wa1, p_wc1, 64, 152, 152, 208);
    k_wc<<<dim3(3, 152), 128>>>(Wm2, bm2, Wa2, p_wc2, 152, 152, 152, 384);
    k_wc<<<dim3(3, 64), 128>>>(Wm3, bm3, Wa3, p_wc3, 152, 64, 64, 384);

    // ---- layer 1 (64 -> 152) ----
    k_gather<16, 64, 208><<<GW, 256>>>(nf, 64, p_xc1);
    k_gemm_bf<<<dim3(NP / 128, 3), 256>>>(p_xc1, p_wc1, ba1, p_h1, NN, 152, 208, HID);

    // ---- layer 2 (152 -> 152) ----
    k_gather<38, 152, 384><<<GW, 256>>>(p_h1, HID, p_xc2);
    k_gemm_bf<<<dim3(NP / 128, 3), 256>>>(p_xc2, p_wc2, ba2, p_h2, NN, 152, 384, HID);

    // ---- layer 3 (152 -> 64) ----
    k_gather<38, 152, 384><<<GW, 256>>>(p_h2, HID, p_xc2);
    k_gemm_bf<<<dim3(NP / 128, 1), 256>>>(p_xc2, p_wc3, ba3, out, NN, 64, 384, 64);
}